// round 3
// baseline (speedup 1.0000x reference)
#include <cuda_runtime.h>

// ---------------------------------------------------------------------------
// Problem constants
// ---------------------------------------------------------------------------
constexpr int NB  = 8;     // batches
constexpr int NN  = 2048;  // boxes per batch
constexpr int NC  = 91;    // classes
constexpr int NCM = 90;    // classes - 1
constexpr int NP  = 1024;  // feature dim
constexpr int NK  = 128;   // TOP_K
constexpr int CAND_CAP = 16384;
#define IOU_THR 0.7f

// ---------------------------------------------------------------------------
// Device scratch (static __device__ globals: allowed, no allocation)
// ---------------------------------------------------------------------------
__device__ float g_S  [(size_t)NB * NN * NP];   // 64 MB
__device__ float g_O  [(size_t)NB * NN * NP];   // 64 MB
__device__ float g_RAW[(size_t)NB * NN * NN];   // 128 MB
__device__ float g_WtS[NCM * NP];
__device__ float g_WtO[NCM * NP];
__device__ unsigned int       g_hist[NB][4096];
__device__ unsigned int       g_thresh[NB];
__device__ unsigned int       g_cnt[NB];
__device__ unsigned long long g_cand[NB][CAND_CAP];

__device__ __forceinline__ unsigned int mono_key(float f) {
    unsigned int u = __float_as_uint(f);
    return (u & 0x80000000u) ? ~u : (u | 0x80000000u);
}

// ---------------------------------------------------------------------------
// K0: transpose W matrices, zero histograms / counters
// ---------------------------------------------------------------------------
__global__ void k_init(const float* __restrict__ Ws, const float* __restrict__ Wo) {
    int idx = blockIdx.x * 256 + threadIdx.x;
    if (idx < NCM * NP) {
        int p = idx / NCM, c = idx % NCM;
        g_WtS[c * NP + p] = Ws[idx];
        g_WtO[c * NP + p] = Wo[idx];
    }
    if (idx < NB * 4096) ((unsigned int*)g_hist)[idx] = 0;
    if (idx < NB)        g_cnt[idx] = 0;
}

// ---------------------------------------------------------------------------
// K1: gates  s = (scores[:, :90] @ W_s^T + b_s) * f ; same for o
// tile: 32 rows x 256 p-cols per block; thread = 4 rows x 8 p
// grid: (NP/256, NN/32, NB), 256 threads
// ---------------------------------------------------------------------------
__global__ void __launch_bounds__(256, 2)
k_gates(const float* __restrict__ scores, const float* __restrict__ features,
        const float* __restrict__ bsub,   const float* __restrict__ bobj) {
    __shared__ float sc[32 * NCM];
    int b  = blockIdx.z;
    int r0 = blockIdx.y * 32;
    int p0 = blockIdx.x * 256;
    int tid = threadIdx.x;

    for (int x = tid; x < 32 * NCM; x += 256) {
        int r = x / NCM, c = x % NCM;
        sc[x] = scores[((size_t)(b * NN + r0 + r)) * NC + c];
    }
    __syncthreads();

    int px = tid & 31;          // p lane
    int ry = tid >> 5;          // warp id -> row group
    int pb = p0 + px * 8;

    float aS[4][8], aO[4][8];
#pragma unroll
    for (int i = 0; i < 4; i++)
#pragma unroll
        for (int j = 0; j < 8; j++) { aS[i][j] = 0.f; aO[i][j] = 0.f; }

    for (int c = 0; c < NCM; c++) {
        float ws[8], wo[8];
        *(float4*)&ws[0] = *(const float4*)&g_WtS[c * NP + pb];
        *(float4*)&ws[4] = *(const float4*)&g_WtS[c * NP + pb + 4];
        *(float4*)&wo[0] = *(const float4*)&g_WtO[c * NP + pb];
        *(float4*)&wo[4] = *(const float4*)&g_WtO[c * NP + pb + 4];
#pragma unroll
        for (int rr = 0; rr < 4; rr++) {
            float v = sc[(ry * 4 + rr) * NCM + c];
#pragma unroll
            for (int j = 0; j < 8; j++) {
                aS[rr][j] = fmaf(v, ws[j], aS[rr][j]);
                aO[rr][j] = fmaf(v, wo[j], aO[rr][j]);
            }
        }
    }

    float bS[8], bO[8];
    *(float4*)&bS[0] = *(const float4*)&bsub[pb];
    *(float4*)&bS[4] = *(const float4*)&bsub[pb + 4];
    *(float4*)&bO[0] = *(const float4*)&bobj[pb];
    *(float4*)&bO[4] = *(const float4*)&bobj[pb + 4];

#pragma unroll
    for (int rr = 0; rr < 4; rr++) {
        int r = r0 + ry * 4 + rr;
        size_t base = ((size_t)b * NN + r) * NP + pb;
        float fv[8];
        *(float4*)&fv[0] = *(const float4*)&features[base];
        *(float4*)&fv[4] = *(const float4*)&features[base + 4];
        float so[8], oo[8];
#pragma unroll
        for (int j = 0; j < 8; j++) {
            so[j] = (aS[rr][j] + bS[j]) * fv[j];
            oo[j] = (aO[rr][j] + bO[j]) * fv[j];
        }
        *(float4*)&g_S[base]     = *(float4*)&so[0];
        *(float4*)&g_S[base + 4] = *(float4*)&so[4];
        *(float4*)&g_O[base]     = *(float4*)&oo[0];
        *(float4*)&g_O[base + 4] = *(float4*)&oo[4];
    }
}

// ---------------------------------------------------------------------------
// K2: raw = S @ O^T, upper-triangular tiles only (tj >= ti)
// 128x128 tile, BK=16, 256 threads, 8x8 per thread
// double-buffered smem: ONE __syncthreads per K-tile
// grid: (136, NB)
// ---------------------------------------------------------------------------
__global__ void __launch_bounds__(256, 2) k_gemm() {
    int b = blockIdx.y;
    int t = blockIdx.x;                 // 0..135 -> (ti, tj) with tj >= ti
    int ti = 0;
    while (t >= 16 - ti) { t -= 16 - ti; ti++; }
    int tj = ti + t;

    const float* Sb = g_S + (size_t)b * NN * NP + (size_t)ti * 128 * NP;
    const float* Ob = g_O + (size_t)b * NN * NP + (size_t)tj * 128 * NP;
    float* Rb = g_RAW + (size_t)b * NN * NN;

    __shared__ float As[2][16][128];
    __shared__ float Bs[2][16][128];

    int tid = threadIdx.x;
    int lr = tid >> 1;                  // 0..127 load row
    int lc = (tid & 1) * 8;             // 0 or 8
    int tx = tid & 15, ty = tid >> 4;

    float acc[8][8];
#pragma unroll
    for (int i = 0; i < 8; i++)
#pragma unroll
        for (int j = 0; j < 8; j++) acc[i][j] = 0.f;

    // prime: tile 0 -> smem[0]
    {
        const float* sa = Sb + (size_t)lr * NP + lc;
        const float* so = Ob + (size_t)lr * NP + lc;
        float4 a0 = *(const float4*)sa, a1 = *(const float4*)(sa + 4);
        float4 b0 = *(const float4*)so, b1 = *(const float4*)(so + 4);
        As[0][lc + 0][lr] = a0.x; As[0][lc + 1][lr] = a0.y;
        As[0][lc + 2][lr] = a0.z; As[0][lc + 3][lr] = a0.w;
        As[0][lc + 4][lr] = a1.x; As[0][lc + 5][lr] = a1.y;
        As[0][lc + 6][lr] = a1.z; As[0][lc + 7][lr] = a1.w;
        Bs[0][lc + 0][lr] = b0.x; Bs[0][lc + 1][lr] = b0.y;
        Bs[0][lc + 2][lr] = b0.z; Bs[0][lc + 3][lr] = b0.w;
        Bs[0][lc + 4][lr] = b1.x; Bs[0][lc + 5][lr] = b1.y;
        Bs[0][lc + 6][lr] = b1.z; Bs[0][lc + 7][lr] = b1.w;
    }
    __syncthreads();

    for (int kt = 0; kt < 64; kt++) {
        int cur = kt & 1, nxt = cur ^ 1;

        float4 pa0, pa1, pb0, pb1;
        if (kt < 63) {
            const float* sa = Sb + (size_t)lr * NP + (kt + 1) * 16 + lc;
            const float* so = Ob + (size_t)lr * NP + (kt + 1) * 16 + lc;
            pa0 = *(const float4*)sa;  pa1 = *(const float4*)(sa + 4);
            pb0 = *(const float4*)so;  pb1 = *(const float4*)(so + 4);
        }

#pragma unroll
        for (int k = 0; k < 16; k++) {
            float av[8], bv[8];
            *(float4*)&av[0] = *(float4*)&As[cur][k][ty * 8];
            *(float4*)&av[4] = *(float4*)&As[cur][k][ty * 8 + 4];
            *(float4*)&bv[0] = *(float4*)&Bs[cur][k][tx * 8];
            *(float4*)&bv[4] = *(float4*)&Bs[cur][k][tx * 8 + 4];
#pragma unroll
            for (int i = 0; i < 8; i++)
#pragma unroll
                for (int j = 0; j < 8; j++)
                    acc[i][j] = fmaf(av[i], bv[j], acc[i][j]);
        }

        if (kt < 63) {
            As[nxt][lc + 0][lr] = pa0.x; As[nxt][lc + 1][lr] = pa0.y;
            As[nxt][lc + 2][lr] = pa0.z; As[nxt][lc + 3][lr] = pa0.w;
            As[nxt][lc + 4][lr] = pa1.x; As[nxt][lc + 5][lr] = pa1.y;
            As[nxt][lc + 6][lr] = pa1.z; As[nxt][lc + 7][lr] = pa1.w;
            Bs[nxt][lc + 0][lr] = pb0.x; Bs[nxt][lc + 1][lr] = pb0.y;
            Bs[nxt][lc + 2][lr] = pb0.z; Bs[nxt][lc + 3][lr] = pb0.w;
            Bs[nxt][lc + 4][lr] = pb1.x; Bs[nxt][lc + 5][lr] = pb1.y;
            Bs[nxt][lc + 6][lr] = pb1.z; Bs[nxt][lc + 7][lr] = pb1.w;
        }
        __syncthreads();
    }

#pragma unroll
    for (int i = 0; i < 8; i++) {
        size_t ro = (size_t)(ti * 128 + ty * 8 + i) * NN + tj * 128 + tx * 8;
        float4 v0 = make_float4(acc[i][0], acc[i][1], acc[i][2], acc[i][3]);
        float4 v1 = make_float4(acc[i][4], acc[i][5], acc[i][6], acc[i][7]);
        *(float4*)&Rb[ro]     = v0;
        *(float4*)&Rb[ro + 4] = v1;
    }
}

// ---------------------------------------------------------------------------
// K3: 12-bit-key histogram over upper triangle (per batch)
// grid: (NN/16, NB), 256 threads
// ---------------------------------------------------------------------------
__global__ void k_hist() {
    __shared__ unsigned int h[4096];
    int b  = blockIdx.y;
    int i0 = blockIdx.x * 16;
    for (int x = threadIdx.x; x < 4096; x += 256) h[x] = 0;
    __syncthreads();

    const float* Rb = g_RAW + (size_t)b * NN * NN;
    int lane = threadIdx.x & 31;
    for (int r = 0; r < 16; r++) {
        int i = i0 + r;
        int total = NN - (i + 1);
        int iters = (total + 255) / 256;
        for (int it = 0; it < iters; it++) {
            int j = i + 1 + it * 256 + threadIdx.x;
            bool valid = j < NN;
            unsigned int bin = valid ? (mono_key(Rb[(size_t)i * NN + j]) >> 20)
                                     : 0xFFFFFFFFu;
            unsigned int mask = __match_any_sync(0xFFFFFFFFu, bin);
            int leader = __ffs(mask) - 1;
            if (valid && lane == leader) atomicAdd(&h[bin], __popc(mask));
        }
    }
    __syncthreads();
    for (int x = threadIdx.x; x < 4096; x += 256)
        if (h[x]) atomicAdd(&g_hist[b][x], h[x]);
}

// ---------------------------------------------------------------------------
// K4: pick bin containing rank-128 (from the top)
// ---------------------------------------------------------------------------
__global__ void k_select() {
    int b = threadIdx.x;
    if (b < NB) {
        unsigned int cum = 0;
        int bin = 4095;
        for (; bin > 0; bin--) {
            cum += g_hist[b][bin];
            if (cum >= NK) break;
        }
        g_thresh[b] = (unsigned int)bin << 20;
    }
}

// ---------------------------------------------------------------------------
// K5: collect candidates with raw-key >= threshold; pack (sigmoid-key, ~idx)
// ---------------------------------------------------------------------------
__global__ void k_collect() {
    int b  = blockIdx.y;
    int i0 = blockIdx.x * 16;
    unsigned int th = g_thresh[b];
    const float* Rb = g_RAW + (size_t)b * NN * NN;
    for (int r = 0; r < 16; r++) {
        int i = i0 + r;
        for (int j = i + 1 + threadIdx.x; j < NN; j += 256) {
            float v = Rb[(size_t)i * NN + j];
            if (mono_key(v) >= th) {
                float sg = 1.0f / (1.0f + expf(-v));
                unsigned int skey = __float_as_uint(sg) | 0x80000000u; // sg > 0
                unsigned int pos = atomicAdd(&g_cnt[b], 1u);
                if (pos < CAND_CAP)
                    g_cand[b][pos] = ((unsigned long long)skey << 32)
                                   | (unsigned long long)(0xFFFFFFFFu - (unsigned)(i * NN + j));
            }
        }
    }
}

// ---------------------------------------------------------------------------
// helper IoU (fp32, matches reference formula)
// ---------------------------------------------------------------------------
__device__ __forceinline__ float iou4(const float* A, const float* Bx) {
    float a1 = fmaxf(A[2] - A[0], 0.f) * fmaxf(A[3] - A[1], 0.f);
    float a2 = fmaxf(Bx[2] - Bx[0], 0.f) * fmaxf(Bx[3] - Bx[1], 0.f);
    float lx = fmaxf(A[0], Bx[0]), ly = fmaxf(A[1], Bx[1]);
    float rx = fminf(A[2], Bx[2]), ry = fminf(A[3], Bx[3]);
    float w = fmaxf(rx - lx, 0.f), h = fmaxf(ry - ly, 0.f);
    float inter = w * h;
    return inter / (a1 + a2 - inter + 1e-9f);
}

// ---------------------------------------------------------------------------
// K6: per-batch block: bitonic sort candidates -> top-128 -> NMS -> gather
// grid: (NB), 256 threads, dyn smem = CAND_CAP * 8 bytes
// ---------------------------------------------------------------------------
__global__ void k_final(const float* __restrict__ boxes,
                        const float* __restrict__ scores,
                        const float* __restrict__ features,
                        float* __restrict__ out) {
    extern __shared__ unsigned long long cand[];
    __shared__ float sbx[NK][4], obx[NK][4];
    __shared__ int   subj[NK], obj[NK], keep[NK], sel[NK];

    int b = blockIdx.x;
    int tid = threadIdx.x;
    unsigned int cnt = g_cnt[b];
    int n = (cnt < CAND_CAP) ? (int)cnt : CAND_CAP;
    int M = 128;
    while (M < n) M <<= 1;

    for (int i = tid; i < M; i += 256)
        cand[i] = (i < n) ? g_cand[b][i] : 0ULL;
    __syncthreads();

    // bitonic sort, descending by (sigmoid key, then ascending flat index)
    for (int size = 2; size <= M; size <<= 1) {
        for (int stride = size >> 1; stride > 0; stride >>= 1) {
            for (int i = tid; i < M; i += 256) {
                int j = i ^ stride;
                if (j > i) {
                    unsigned long long a = cand[i], c2 = cand[j];
                    bool desc = ((i & size) == 0);
                    if (desc ? (a < c2) : (a > c2)) { cand[i] = c2; cand[j] = a; }
                }
            }
            __syncthreads();
        }
    }

    if (tid < NK) {
        // flat index < 2^22 always; mask keeps padded entries in-range
        unsigned int fl = (0xFFFFFFFFu - (unsigned)(cand[tid] & 0xFFFFFFFFu)) & 0x3FFFFFu;
        int si = fl >> 11;          // / 2048
        int oj = fl & 2047;         // % 2048
        subj[tid] = si; obj[tid] = oj;
        const float* bb = boxes + (size_t)b * NN * 4;
#pragma unroll
        for (int d = 0; d < 4; d++) {
            sbx[tid][d] = bb[si * 4 + d];
            obx[tid][d] = bb[oj * 4 + d];
        }
        keep[tid] = 1;
    }
    __syncthreads();

    // greedy pair-NMS
    for (int i = 0; i < NK; i++) {
        int ki = keep[i];
        if (tid < NK && tid > i && ki && keep[tid]) {
            float is = iou4(sbx[i], sbx[tid]);
            float io = iou4(obx[i], obx[tid]);
            if (is > IOU_THR && io > IOU_THR) keep[tid] = 0;
        }
        __syncthreads();
    }

    if (tid < NK) {
        float ps = sbx[tid][0] - sbx[tid][1]; ps *= ps;
        float po = obx[tid][0] - obx[tid][1]; po *= po;
        sel[tid] = (ps >= po) ? subj[tid] : obj[tid];   // argmax ties -> first
    }
    __syncthreads();

    const size_t OFF_F = (size_t)NB * NK * 8;
    const size_t OFF_S = OFF_F + (size_t)NB * NK * NP;

    // out_boxes [B, K, 2, 4]
    for (int x = tid; x < NK * 8; x += 256) {
        int k = x >> 3, d = x & 7;
        float m = keep[k] ? 1.f : 0.f;
        float v = (d < 4) ? sbx[k][d] : obx[k][d - 4];
        out[((size_t)b * NK + k) * 8 + d] = v * m;
    }
    // out_feats [B, K, 1024]
    for (int x = tid; x < NK * NP; x += 256) {
        int k = x >> 10, p = x & 1023;
        float m = keep[k] ? 1.f : 0.f;
        out[OFF_F + ((size_t)b * NK + k) * NP + p] =
            features[((size_t)b * NN + sel[k]) * NP + p] * m;
    }
    // out_scores [B, K, 91]
    for (int x = tid; x < NK * NC; x += 256) {
        int k = x / NC, c = x % NC;
        float m = keep[k] ? 1.f : 0.f;
        out[OFF_S + ((size_t)b * NK + k) * NC + c] =
            scores[((size_t)b * NN + sel[k]) * NC + c] * m;
    }
}

// ---------------------------------------------------------------------------
// launch
// ---------------------------------------------------------------------------
extern "C" void kernel_launch(void* const* d_in, const int* in_sizes, int n_in,
                              void* d_out, int out_size) {
    const float* boxes    = (const float*)d_in[0];
    const float* scores   = (const float*)d_in[1];
    const float* features = (const float*)d_in[2];
    const float* Ws       = (const float*)d_in[3];
    const float* bs       = (const float*)d_in[4];
    const float* Wo       = (const float*)d_in[5];
    const float* bo       = (const float*)d_in[6];
    float* out = (float*)d_out;
    (void)in_sizes; (void)n_in; (void)out_size;

    cudaFuncSetAttribute(k_final, cudaFuncAttributeMaxDynamicSharedMemorySize,
                         CAND_CAP * 8);

    k_init<<<(NCM * NP + 255) / 256, 256>>>(Ws, Wo);
    k_gates<<<dim3(NP / 256, NN / 32, NB), 256>>>(scores, features, bs, bo);
    k_gemm<<<dim3(136, NB), 256>>>();
    k_hist<<<dim3(NN / 16, NB), 256>>>();
    k_select<<<1, 32>>>();
    k_collect<<<dim3(NN / 16, NB), 256>>>();
    k_final<<<NB, 256, CAND_CAP * 8>>>(boxes, scores, features, out);
}

// round 6
// speedup vs baseline: 1.4094x; 1.4094x over previous
#include <cuda_runtime.h>
#include <cuda_bf16.h>
#include <cstdint>

// ---------------------------------------------------------------------------
// Problem constants
// ---------------------------------------------------------------------------
constexpr int NB  = 8;     // batches
constexpr int NN  = 2048;  // boxes per batch
constexpr int NC  = 91;    // classes
constexpr int NCM = 90;    // classes - 1
constexpr int NP  = 1024;  // feature dim
constexpr int NK  = 128;   // TOP_K
constexpr int CAND_CAP = 16384;
#define IOU_THR 0.7f

// ---------------------------------------------------------------------------
// Device scratch
// ---------------------------------------------------------------------------
__device__ float g_S  [(size_t)NB * NN * NP];   // fp32 for exact rescore
__device__ float g_O  [(size_t)NB * NN * NP];
__device__ __nv_bfloat16 g_Shi[(size_t)NB * NN * NP];
__device__ __nv_bfloat16 g_Slo[(size_t)NB * NN * NP];
__device__ __nv_bfloat16 g_Ohi[(size_t)NB * NN * NP];
__device__ __nv_bfloat16 g_Olo[(size_t)NB * NN * NP];
__device__ float g_RAW[(size_t)NB * NN * NN];   // approx raw (fp32)
__device__ float g_WtS[NCM * NP];
__device__ float g_WtO[NCM * NP];
__device__ unsigned int       g_hist[NB][4096];
__device__ unsigned int       g_thresh[NB];
__device__ unsigned int       g_cnt[NB];
__device__ unsigned long long g_cand[NB][CAND_CAP];

__device__ __forceinline__ unsigned int mono_key(float f) {
    unsigned int u = __float_as_uint(f);
    return (u & 0x80000000u) ? ~u : (u | 0x80000000u);
}

// ---------------------------------------------------------------------------
// PTX helpers (sm_80-era: mma.sync / ldmatrix / cp.async — valid on sm_100)
// ---------------------------------------------------------------------------
__device__ __forceinline__ uint32_t smem_u32(const void* p) {
    uint32_t a;
    asm("{ .reg .u64 t; cvta.to.shared.u64 t, %1; cvt.u32.u64 %0, t; }"
        : "=r"(a) : "l"(p));
    return a;
}
#define CP_ASYNC16(dst, src) \
    asm volatile("cp.async.ca.shared.global [%0], [%1], 16;" :: "r"(dst), "l"(src))
#define CP_COMMIT()  asm volatile("cp.async.commit_group;" ::: "memory")
#define CP_WAIT(n)   asm volatile("cp.async.wait_group %0;" :: "n"(n) : "memory")

__device__ __forceinline__ void ldsm_x4(uint32_t& r0, uint32_t& r1,
                                        uint32_t& r2, uint32_t& r3, uint32_t a) {
    asm volatile("ldmatrix.sync.aligned.m8n8.x4.shared.b16 {%0,%1,%2,%3}, [%4];"
                 : "=r"(r0), "=r"(r1), "=r"(r2), "=r"(r3) : "r"(a));
}
__device__ __forceinline__ void ldsm_x2(uint32_t& r0, uint32_t& r1, uint32_t a) {
    asm volatile("ldmatrix.sync.aligned.m8n8.x2.shared.b16 {%0,%1}, [%2];"
                 : "=r"(r0), "=r"(r1) : "r"(a));
}
__device__ __forceinline__ void mma16816(float* d, const uint32_t* a,
                                         const uint32_t* b) {
    asm volatile(
        "mma.sync.aligned.m16n8k16.row.col.f32.bf16.bf16.f32 "
        "{%0,%1,%2,%3}, {%4,%5,%6,%7}, {%8,%9}, {%0,%1,%2,%3};"
        : "+f"(d[0]), "+f"(d[1]), "+f"(d[2]), "+f"(d[3])
        : "r"(a[0]), "r"(a[1]), "r"(a[2]), "r"(a[3]), "r"(b[0]), "r"(b[1]));
}

// ---------------------------------------------------------------------------
// K0: transpose W matrices, zero histograms / counters
// ---------------------------------------------------------------------------
__global__ void k_init(const float* __restrict__ Ws, const float* __restrict__ Wo) {
    int idx = blockIdx.x * 256 + threadIdx.x;
    if (idx < NCM * NP) {
        int p = idx / NCM, c = idx % NCM;
        g_WtS[c * NP + p] = Ws[idx];
        g_WtO[c * NP + p] = Wo[idx];
    }
    if (idx < NB * 4096) ((unsigned int*)g_hist)[idx] = 0;
    if (idx < NB)        g_cnt[idx] = 0;
}

// ---------------------------------------------------------------------------
// K1: gates  s = (scores[:, :90] @ W_s^T + b_s) * f
// writes fp32 (for exact rescore) + bf16 hi/lo splits (for HMMA)
// ---------------------------------------------------------------------------
__global__ void __launch_bounds__(256, 2)
k_gates(const float* __restrict__ scores, const float* __restrict__ features,
        const float* __restrict__ bsub,   const float* __restrict__ bobj) {
    __shared__ float sc[32 * NCM];
    int b  = blockIdx.z;
    int r0 = blockIdx.y * 32;
    int p0 = blockIdx.x * 256;
    int tid = threadIdx.x;

    for (int x = tid; x < 32 * NCM; x += 256) {
        int r = x / NCM, c = x % NCM;
        sc[x] = scores[((size_t)(b * NN + r0 + r)) * NC + c];
    }
    __syncthreads();

    int px = tid & 31;
    int ry = tid >> 5;
    int pb = p0 + px * 8;

    float aS[4][8], aO[4][8];
#pragma unroll
    for (int i = 0; i < 4; i++)
#pragma unroll
        for (int j = 0; j < 8; j++) { aS[i][j] = 0.f; aO[i][j] = 0.f; }

    for (int c = 0; c < NCM; c++) {
        float ws[8], wo[8];
        *(float4*)&ws[0] = *(const float4*)&g_WtS[c * NP + pb];
        *(float4*)&ws[4] = *(const float4*)&g_WtS[c * NP + pb + 4];
        *(float4*)&wo[0] = *(const float4*)&g_WtO[c * NP + pb];
        *(float4*)&wo[4] = *(const float4*)&g_WtO[c * NP + pb + 4];
#pragma unroll
        for (int rr = 0; rr < 4; rr++) {
            float v = sc[(ry * 4 + rr) * NCM + c];
#pragma unroll
            for (int j = 0; j < 8; j++) {
                aS[rr][j] = fmaf(v, ws[j], aS[rr][j]);
                aO[rr][j] = fmaf(v, wo[j], aO[rr][j]);
            }
        }
    }

    float bS[8], bO[8];
    *(float4*)&bS[0] = *(const float4*)&bsub[pb];
    *(float4*)&bS[4] = *(const float4*)&bsub[pb + 4];
    *(float4*)&bO[0] = *(const float4*)&bobj[pb];
    *(float4*)&bO[4] = *(const float4*)&bobj[pb + 4];

#pragma unroll
    for (int rr = 0; rr < 4; rr++) {
        int r = r0 + ry * 4 + rr;
        size_t base = ((size_t)b * NN + r) * NP + pb;
        float fv[8];
        *(float4*)&fv[0] = *(const float4*)&features[base];
        *(float4*)&fv[4] = *(const float4*)&features[base + 4];
        float so[8], oo[8];
        __nv_bfloat16 sh[8], sl[8], oh[8], ol[8];
#pragma unroll
        for (int j = 0; j < 8; j++) {
            so[j] = (aS[rr][j] + bS[j]) * fv[j];
            oo[j] = (aO[rr][j] + bO[j]) * fv[j];
            __nv_bfloat16 h1 = __float2bfloat16(so[j]);
            __nv_bfloat16 h2 = __float2bfloat16(oo[j]);
            sh[j] = h1; sl[j] = __float2bfloat16(so[j] - __bfloat162float(h1));
            oh[j] = h2; ol[j] = __float2bfloat16(oo[j] - __bfloat162float(h2));
        }
        *(float4*)&g_S[base]     = *(float4*)&so[0];
        *(float4*)&g_S[base + 4] = *(float4*)&so[4];
        *(float4*)&g_O[base]     = *(float4*)&oo[0];
        *(float4*)&g_O[base + 4] = *(float4*)&oo[4];
        *(uint4*)&g_Shi[base] = *(uint4*)sh;
        *(uint4*)&g_Slo[base] = *(uint4*)sl;
        *(uint4*)&g_Ohi[base] = *(uint4*)oh;
        *(uint4*)&g_Olo[base] = *(uint4*)ol;
    }
}

// ---------------------------------------------------------------------------
// K2: HMMA GEMM  raw ~= S @ O^T via bf16 3-term split, upper-tri tiles only
// 128x128 tile, BK=32, 8 warps (2x4), cp.async double buffer, fused hist
// ---------------------------------------------------------------------------
constexpr int SMEM_GEMM = 2 * 4 * 128 * 32 * 2;   // 65536

__global__ void __launch_bounds__(256, 1) k_gemm_mma() {
    extern __shared__ char smem[];
    uint32_t sb = smem_u32(smem);

    int b = blockIdx.y;
    int t = blockIdx.x;
    int ti = 0;
    while (t >= 16 - ti) { t -= 16 - ti; ti++; }
    int tj = ti + t;

    int tid = threadIdx.x, wid = tid >> 5, lane = tid & 31;
    int wm = wid >> 2, wn = wid & 3;

    const __nv_bfloat16* src[4] = {
        g_Shi + ((size_t)b * NN + ti * 128) * NP,
        g_Slo + ((size_t)b * NN + ti * 128) * NP,
        g_Ohi + ((size_t)b * NN + tj * 128) * NP,
        g_Olo + ((size_t)b * NN + tj * 128) * NP };

    int grow = tid >> 1, ghalf = tid & 1;
    size_t goff = (size_t)grow * NP + ghalf * 16;
    uint32_t sw0 = (uint32_t)grow * 64 + (((ghalf * 2 + 0) ^ (grow & 3)) << 4);
    uint32_t sw1 = (uint32_t)grow * 64 + (((ghalf * 2 + 1) ^ (grow & 3)) << 4);

    float acc[4][4][4];
#pragma unroll
    for (int i = 0; i < 4; i++)
#pragma unroll
        for (int j = 0; j < 4; j++)
#pragma unroll
            for (int q = 0; q < 4; q++) acc[i][j][q] = 0.f;

    int arow = wm * 64 + (lane & 15);
    int acg  = lane >> 4;
    int brow = wn * 32 + (lane & 7);
    int bcg  = (lane >> 3) & 1;

    auto load_buf = [&](int buf, int kc) {
        uint32_t bb = sb + buf * 32768;
#pragma unroll
        for (int m = 0; m < 4; m++) {
            const __nv_bfloat16* gp = src[m] + goff + kc * 32;
            uint32_t sm = bb + m * 8192;
            CP_ASYNC16(sm + sw0, gp);
            CP_ASYNC16(sm + sw1, gp + 8);
        }
    };

    load_buf(0, 0);
    CP_COMMIT();

    for (int kc = 0; kc < 32; kc++) {
        if (kc + 1 < 32) { load_buf((kc + 1) & 1, kc + 1); CP_COMMIT(); }
        if (kc + 1 < 32) { CP_WAIT(1); } else { CP_WAIT(0); }
        __syncthreads();

        uint32_t bb = sb + (kc & 1) * 32768;
#pragma unroll
        for (int ks = 0; ks < 2; ks++) {
            uint32_t aShi[4][4], aSlo[4][4], bOhi[4][2], bOlo[4][2];
#pragma unroll
            for (int im = 0; im < 4; im++) {
                int r = arow + im * 16;
                uint32_t ad = bb + (uint32_t)r * 64 +
                              ((((ks * 2) + acg) ^ (r & 3)) << 4);
                ldsm_x4(aShi[im][0], aShi[im][1], aShi[im][2], aShi[im][3], ad);
                ldsm_x4(aSlo[im][0], aSlo[im][1], aSlo[im][2], aSlo[im][3],
                        ad + 8192);
            }
#pragma unroll
            for (int in = 0; in < 4; in++) {
                int r = brow + in * 8;
                uint32_t bd = bb + 16384 + (uint32_t)r * 64 +
                              ((((ks * 2) + bcg) ^ (r & 3)) << 4);
                ldsm_x2(bOhi[in][0], bOhi[in][1], bd);
                ldsm_x2(bOlo[in][0], bOlo[in][1], bd + 8192);
            }
#pragma unroll
            for (int im = 0; im < 4; im++)
#pragma unroll
                for (int in = 0; in < 4; in++) {
                    mma16816(acc[im][in], aShi[im], bOhi[in]);
                    mma16816(acc[im][in], aShi[im], bOlo[in]);
                    mma16816(acc[im][in], aSlo[im], bOhi[in]);
                }
        }
        __syncthreads();
    }

    // ---- epilogue: store RAW + fused histogram (reuse smem) ----
    unsigned int* shist = (unsigned int*)smem;
    for (int x = tid; x < 4096; x += 256) shist[x] = 0;
    __syncthreads();

    float* Rb = g_RAW + (size_t)b * NN * NN;
    int r0 = ti * 128 + wm * 64 + (lane >> 2);
    int c0 = tj * 128 + wn * 32 + (lane & 3) * 2;
#pragma unroll
    for (int im = 0; im < 4; im++) {
#pragma unroll
        for (int in = 0; in < 4; in++) {
            int gi0 = r0 + im * 16;
            int gj  = c0 + in * 8;
            float* d0 = &Rb[(size_t)gi0 * NN + gj];
            float* d1 = &Rb[(size_t)(gi0 + 8) * NN + gj];
            d0[0] = acc[im][in][0]; d0[1] = acc[im][in][1];
            d1[0] = acc[im][in][2]; d1[1] = acc[im][in][3];
            if (gj     > gi0)     atomicAdd(&shist[mono_key(acc[im][in][0]) >> 20], 1u);
            if (gj + 1 > gi0)     atomicAdd(&shist[mono_key(acc[im][in][1]) >> 20], 1u);
            if (gj     > gi0 + 8) atomicAdd(&shist[mono_key(acc[im][in][2]) >> 20], 1u);
            if (gj + 1 > gi0 + 8) atomicAdd(&shist[mono_key(acc[im][in][3]) >> 20], 1u);
        }
    }
    __syncthreads();
    for (int x = tid; x < 4096; x += 256)
        if (shist[x]) atomicAdd(&g_hist[b][x], shist[x]);
}

// ---------------------------------------------------------------------------
// K4: pick bin containing rank-128 (from the top)
// ---------------------------------------------------------------------------
__global__ void k_select() {
    int b = threadIdx.x;
    if (b < NB) {
        unsigned int cum = 0;
        int bin = 4095;
        for (; bin > 0; bin--) {
            cum += g_hist[b][bin];
            if (cum >= NK) break;
        }
        g_thresh[b] = (unsigned int)bin << 20;
    }
}

// ---------------------------------------------------------------------------
// K5: collect candidates >= threshold (coalesced full-matrix float4 scan)
// key rewritten later by k_rescore; only flat index matters here.
// grid: (NN*NN/1024, NB), 256 threads
// ---------------------------------------------------------------------------
__global__ void k_collect() {
    int b = blockIdx.y;
    size_t x = ((size_t)blockIdx.x * 256 + threadIdx.x) * 4;
    unsigned int th = g_thresh[b];
    const float* Rb = g_RAW + (size_t)b * NN * NN;
    float4 v = *(const float4*)(Rb + x);
    int i = (int)(x >> 11);
    int j = (int)(x & 2047);
    float vv[4] = { v.x, v.y, v.z, v.w };
#pragma unroll
    for (int q = 0; q < 4; q++) {
        if (j + q > i && mono_key(vv[q]) >= th) {
            unsigned int pos = atomicAdd(&g_cnt[b], 1u);
            if (pos < CAND_CAP)
                g_cand[b][pos] =
                    (unsigned long long)(0xFFFFFFFFu - (unsigned)(x + q));
        }
    }
}

// ---------------------------------------------------------------------------
// K5b: exact rescore — one warp per candidate: fp32 dot S[i].O[j] (K=1024),
// sigmoid -> new sort key. grid: (CAND_CAP/8, NB), 256 threads
// ---------------------------------------------------------------------------
__global__ void k_rescore() {
    int b = blockIdx.y;
    unsigned int w = blockIdx.x * 8 + (threadIdx.x >> 5);
    int lane = threadIdx.x & 31;
    unsigned int cnt = g_cnt[b];
    if (cnt > CAND_CAP) cnt = CAND_CAP;
    if (w >= cnt) return;

    unsigned long long e = g_cand[b][w];
    unsigned int low = (unsigned int)e;
    unsigned int fl = (0xFFFFFFFFu - low) & 0x3FFFFFu;
    int i = fl >> 11, j = fl & 2047;

    const float* Si = g_S + ((size_t)b * NN + i) * NP;
    const float* Oj = g_O + ((size_t)b * NN + j) * NP;
    float acc = 0.f;
#pragma unroll
    for (int kk = 0; kk < 8; kk++) {
        float4 a = *(const float4*)&Si[kk * 128 + lane * 4];
        float4 c = *(const float4*)&Oj[kk * 128 + lane * 4];
        acc = fmaf(a.x, c.x, acc);
        acc = fmaf(a.y, c.y, acc);
        acc = fmaf(a.z, c.z, acc);
        acc = fmaf(a.w, c.w, acc);
    }
#pragma unroll
    for (int o = 16; o; o >>= 1) acc += __shfl_xor_sync(0xFFFFFFFFu, acc, o);

    if (lane == 0) {
        float sg = 1.0f / (1.0f + expf(-acc));
        unsigned int skey = __float_as_uint(sg) | 0x80000000u;
        g_cand[b][w] = ((unsigned long long)skey << 32) | low;
    }
}

// ---------------------------------------------------------------------------
// helper IoU
// ---------------------------------------------------------------------------
__device__ __forceinline__ float iou4(const float* A, const float* Bx) {
    float a1 = fmaxf(A[2] - A[0], 0.f) * fmaxf(A[3] - A[1], 0.f);
    float a2 = fmaxf(Bx[2] - Bx[0], 0.f) * fmaxf(Bx[3] - Bx[1], 0.f);
    float lx = fmaxf(A[0], Bx[0]), ly = fmaxf(A[1], Bx[1]);
    float rx = fminf(A[2], Bx[2]), ry = fminf(A[3], Bx[3]);
    float w = fmaxf(rx - lx, 0.f), h = fmaxf(ry - ly, 0.f);
    float inter = w * h;
    return inter / (a1 + a2 - inter + 1e-9f);
}

// ---------------------------------------------------------------------------
// K6: per-batch: bitonic sort candidates -> top-128 -> NMS -> gather
// ---------------------------------------------------------------------------
__global__ void k_final(const float* __restrict__ boxes,
                        const float* __restrict__ scores,
                        const float* __restrict__ features,
                        float* __restrict__ out) {
    extern __shared__ unsigned long long cand[];
    __shared__ float sbx[NK][4], obx[NK][4];
    __shared__ int   subj[NK], obj[NK], keep[NK], sel[NK];

    int b = blockIdx.x;
    int tid = threadIdx.x;
    unsigned int cnt = g_cnt[b];
    int n = (cnt < CAND_CAP) ? (int)cnt : CAND_CAP;
    int M = 128;
    while (M < n) M <<= 1;

    for (int i = tid; i < M; i += 256)
        cand[i] = (i < n) ? g_cand[b][i] : 0ULL;
    __syncthreads();

    for (int size = 2; size <= M; size <<= 1) {
        for (int stride = size >> 1; stride > 0; stride >>= 1) {
            for (int i = tid; i < M; i += 256) {
                int j = i ^ stride;
                if (j > i) {
                    unsigned long long a = cand[i], c2 = cand[j];
                    bool desc = ((i & size) == 0);
                    if (desc ? (a < c2) : (a > c2)) { cand[i] = c2; cand[j] = a; }
                }
            }
            __syncthreads();
        }
    }

    if (tid < NK) {
        unsigned int fl = (0xFFFFFFFFu - (unsigned)(cand[tid] & 0xFFFFFFFFu)) & 0x3FFFFFu;
        int si = fl >> 11;
        int oj = fl & 2047;
        subj[tid] = si; obj[tid] = oj;
        const float* bb = boxes + (size_t)b * NN * 4;
#pragma unroll
        for (int d = 0; d < 4; d++) {
            sbx[tid][d] = bb[si * 4 + d];
            obx[tid][d] = bb[oj * 4 + d];
        }
        keep[tid] = 1;
    }
    __syncthreads();

    for (int i = 0; i < NK; i++) {
        int ki = keep[i];
        if (tid < NK && tid > i && ki && keep[tid]) {
            float is = iou4(sbx[i], sbx[tid]);
            float io = iou4(obx[i], obx[tid]);
            if (is > IOU_THR && io > IOU_THR) keep[tid] = 0;
        }
        __syncthreads();
    }

    if (tid < NK) {
        float ps = sbx[tid][0] - sbx[tid][1]; ps *= ps;
        float po = obx[tid][0] - obx[tid][1]; po *= po;
        sel[tid] = (ps >= po) ? subj[tid] : obj[tid];
    }
    __syncthreads();

    const size_t OFF_F = (size_t)NB * NK * 8;
    const size_t OFF_S = OFF_F + (size_t)NB * NK * NP;

    for (int x = tid; x < NK * 8; x += 256) {
        int k = x >> 3, d = x & 7;
        float m = keep[k] ? 1.f : 0.f;
        float v = (d < 4) ? sbx[k][d] : obx[k][d - 4];
        out[((size_t)b * NK + k) * 8 + d] = v * m;
    }
    for (int x = tid; x < NK * NP; x += 256) {
        int k = x >> 10, p = x & 1023;
        float m = keep[k] ? 1.f : 0.f;
        out[OFF_F + ((size_t)b * NK + k) * NP + p] =
            features[((size_t)b * NN + sel[k]) * NP + p] * m;
    }
    for (int x = tid; x < NK * NC; x += 256) {
        int k = x / NC, c = x % NC;
        float m = keep[k] ? 1.f : 0.f;
        out[OFF_S + ((size_t)b * NK + k) * NC + c] =
            scores[((size_t)b * NN + sel[k]) * NC + c] * m;
    }
}

// ---------------------------------------------------------------------------
// launch
// ---------------------------------------------------------------------------
extern "C" void kernel_launch(void* const* d_in, const int* in_sizes, int n_in,
                              void* d_out, int out_size) {
    const float* boxes    = (const float*)d_in[0];
    const float* scores   = (const float*)d_in[1];
    const float* features = (const float*)d_in[2];
    const float* Ws       = (const float*)d_in[3];
    const float* bs       = (const float*)d_in[4];
    const float* Wo       = (const float*)d_in[5];
    const float* bo       = (const float*)d_in[6];
    float* out = (float*)d_out;
    (void)in_sizes; (void)n_in; (void)out_size;

    cudaFuncSetAttribute(k_gemm_mma, cudaFuncAttributeMaxDynamicSharedMemorySize,
                         SMEM_GEMM);
    cudaFuncSetAttribute(k_final, cudaFuncAttributeMaxDynamicSharedMemorySize,
                         CAND_CAP * 8);

    k_init<<<(NCM * NP + 255) / 256, 256>>>(Ws, Wo);
    k_gates<<<dim3(NP / 256, NN / 32, NB), 256>>>(scores, features, bs, bo);
    k_gemm_mma<<<dim3(136, NB), 256, SMEM_GEMM>>>();
    k_select<<<1, 32>>>();
    k_collect<<<dim3(NN * NN / 1024, NB), 256>>>();
    k_rescore<<<dim3(CAND_CAP / 8, NB), 256>>>();
    k_final<<<NB, 256, CAND_CAP * 8>>>(boxes, scores, features, out);
}

// round 7
// speedup vs baseline: 2.0239x; 1.4360x over previous
#include <cuda_runtime.h>
#include <cuda_bf16.h>
#include <cstdint>

// ---------------------------------------------------------------------------
// Problem constants
// ---------------------------------------------------------------------------
constexpr int NB  = 8;     // batches
constexpr int NN  = 2048;  // boxes per batch
constexpr int NC  = 91;    // classes
constexpr int NCM = 90;    // classes - 1
constexpr int NP  = 1024;  // feature dim
constexpr int NK  = 128;   // TOP_K
constexpr int CAND_CAP = 16384;
#define IOU_THR 0.7f

// ---------------------------------------------------------------------------
// Device scratch
// ---------------------------------------------------------------------------
__device__ float g_S  [(size_t)NB * NN * NP];   // fp32 for exact rescore
__device__ float g_O  [(size_t)NB * NN * NP];
__device__ __nv_bfloat16 g_Shi[(size_t)NB * NN * NP];
__device__ __nv_bfloat16 g_Ohi[(size_t)NB * NN * NP];
__device__ float g_RAW[(size_t)NB * NN * NN];   // approx raw (fp32)
__device__ float g_WtS[NCM * NP];
__device__ float g_WtO[NCM * NP];
__device__ unsigned int       g_hist[NB][4096];
__device__ unsigned int       g_thresh[NB];
__device__ unsigned int       g_cnt[NB];
__device__ unsigned long long g_cand[NB][CAND_CAP];

__device__ __forceinline__ unsigned int mono_key(float f) {
    unsigned int u = __float_as_uint(f);
    return (u & 0x80000000u) ? ~u : (u | 0x80000000u);
}

// ---------------------------------------------------------------------------
// PTX helpers (sm_80-era: mma.sync / ldmatrix / cp.async — valid on sm_100)
// ---------------------------------------------------------------------------
__device__ __forceinline__ uint32_t smem_u32(const void* p) {
    uint32_t a;
    asm("{ .reg .u64 t; cvta.to.shared.u64 t, %1; cvt.u32.u64 %0, t; }"
        : "=r"(a) : "l"(p));
    return a;
}
#define CP_ASYNC16(dst, src) \
    asm volatile("cp.async.ca.shared.global [%0], [%1], 16;" :: "r"(dst), "l"(src))
#define CP_COMMIT()  asm volatile("cp.async.commit_group;" ::: "memory")
#define CP_WAIT(n)   asm volatile("cp.async.wait_group %0;" :: "n"(n) : "memory")

__device__ __forceinline__ void ldsm_x4(uint32_t& r0, uint32_t& r1,
                                        uint32_t& r2, uint32_t& r3, uint32_t a) {
    asm volatile("ldmatrix.sync.aligned.m8n8.x4.shared.b16 {%0,%1,%2,%3}, [%4];"
                 : "=r"(r0), "=r"(r1), "=r"(r2), "=r"(r3) : "r"(a));
}
__device__ __forceinline__ void ldsm_x2(uint32_t& r0, uint32_t& r1, uint32_t a) {
    asm volatile("ldmatrix.sync.aligned.m8n8.x2.shared.b16 {%0,%1}, [%2];"
                 : "=r"(r0), "=r"(r1) : "r"(a));
}
__device__ __forceinline__ void mma16816(float* d, const uint32_t* a,
                                         const uint32_t* b) {
    asm volatile(
        "mma.sync.aligned.m16n8k16.row.col.f32.bf16.bf16.f32 "
        "{%0,%1,%2,%3}, {%4,%5,%6,%7}, {%8,%9}, {%0,%1,%2,%3};"
        : "+f"(d[0]), "+f"(d[1]), "+f"(d[2]), "+f"(d[3])
        : "r"(a[0]), "r"(a[1]), "r"(a[2]), "r"(a[3]), "r"(b[0]), "r"(b[1]));
}

// ---------------------------------------------------------------------------
// K0: transpose W matrices, zero histograms / counters
// ---------------------------------------------------------------------------
__global__ void k_init(const float* __restrict__ Ws, const float* __restrict__ Wo) {
    int idx = blockIdx.x * 256 + threadIdx.x;
    if (idx < NCM * NP) {
        int p = idx / NCM, c = idx % NCM;
        g_WtS[c * NP + p] = Ws[idx];
        g_WtO[c * NP + p] = Wo[idx];
    }
    if (idx < NB * 4096) ((unsigned int*)g_hist)[idx] = 0;
    if (idx < NB)        g_cnt[idx] = 0;
}

// ---------------------------------------------------------------------------
// K1: gates  s = (scores[:, :90] @ W_s^T + b_s) * f
// writes fp32 (exact rescore) + bf16 (HMMA approx)
// ---------------------------------------------------------------------------
__global__ void __launch_bounds__(256, 2)
k_gates(const float* __restrict__ scores, const float* __restrict__ features,
        const float* __restrict__ bsub,   const float* __restrict__ bobj) {
    __shared__ float sc[32 * NCM];
    int b  = blockIdx.z;
    int r0 = blockIdx.y * 32;
    int p0 = blockIdx.x * 256;
    int tid = threadIdx.x;

    for (int x = tid; x < 32 * NCM; x += 256) {
        int r = x / NCM, c = x % NCM;
        sc[x] = scores[((size_t)(b * NN + r0 + r)) * NC + c];
    }
    __syncthreads();

    int px = tid & 31;
    int ry = tid >> 5;
    int pb = p0 + px * 8;

    float aS[4][8], aO[4][8];
#pragma unroll
    for (int i = 0; i < 4; i++)
#pragma unroll
        for (int j = 0; j < 8; j++) { aS[i][j] = 0.f; aO[i][j] = 0.f; }

    for (int c = 0; c < NCM; c++) {
        float ws[8], wo[8];
        *(float4*)&ws[0] = *(const float4*)&g_WtS[c * NP + pb];
        *(float4*)&ws[4] = *(const float4*)&g_WtS[c * NP + pb + 4];
        *(float4*)&wo[0] = *(const float4*)&g_WtO[c * NP + pb];
        *(float4*)&wo[4] = *(const float4*)&g_WtO[c * NP + pb + 4];
#pragma unroll
        for (int rr = 0; rr < 4; rr++) {
            float v = sc[(ry * 4 + rr) * NCM + c];
#pragma unroll
            for (int j = 0; j < 8; j++) {
                aS[rr][j] = fmaf(v, ws[j], aS[rr][j]);
                aO[rr][j] = fmaf(v, wo[j], aO[rr][j]);
            }
        }
    }

    float bS[8], bO[8];
    *(float4*)&bS[0] = *(const float4*)&bsub[pb];
    *(float4*)&bS[4] = *(const float4*)&bsub[pb + 4];
    *(float4*)&bO[0] = *(const float4*)&bobj[pb];
    *(float4*)&bO[4] = *(const float4*)&bobj[pb + 4];

#pragma unroll
    for (int rr = 0; rr < 4; rr++) {
        int r = r0 + ry * 4 + rr;
        size_t base = ((size_t)b * NN + r) * NP + pb;
        float fv[8];
        *(float4*)&fv[0] = *(const float4*)&features[base];
        *(float4*)&fv[4] = *(const float4*)&features[base + 4];
        float so[8], oo[8];
        __nv_bfloat16 sh[8], oh[8];
#pragma unroll
        for (int j = 0; j < 8; j++) {
            so[j] = (aS[rr][j] + bS[j]) * fv[j];
            oo[j] = (aO[rr][j] + bO[j]) * fv[j];
            sh[j] = __float2bfloat16(so[j]);
            oh[j] = __float2bfloat16(oo[j]);
        }
        *(float4*)&g_S[base]     = *(float4*)&so[0];
        *(float4*)&g_S[base + 4] = *(float4*)&so[4];
        *(float4*)&g_O[base]     = *(float4*)&oo[0];
        *(float4*)&g_O[base + 4] = *(float4*)&oo[4];
        *(uint4*)&g_Shi[base] = *(uint4*)sh;
        *(uint4*)&g_Ohi[base] = *(uint4*)oh;
    }
}

// ---------------------------------------------------------------------------
// K2: HMMA GEMM  raw ~= S @ O^T (single-term bf16), upper-tri tiles only
// 128x128 tile, BK=64, 8 warps (2x4), cp.async double buffer, fused hist
// smem: 2 buffers x 2 matrices x 128 rows x 128 bytes = 64 KB
// ---------------------------------------------------------------------------
constexpr int SMEM_GEMM = 2 * 2 * 128 * 128;   // 65536

__global__ void __launch_bounds__(256, 2) k_gemm_mma() {
    extern __shared__ char smem[];
    uint32_t sb = smem_u32(smem);

    int b = blockIdx.y;
    int t = blockIdx.x;
    int ti = 0;
    while (t >= 16 - ti) { t -= 16 - ti; ti++; }
    int tj = ti + t;

    int tid = threadIdx.x, wid = tid >> 5, lane = tid & 31;
    int wm = wid >> 2, wn = wid & 3;

    const __nv_bfloat16* srcA = g_Shi + ((size_t)b * NN + ti * 128) * NP;
    const __nv_bfloat16* srcB = g_Ohi + ((size_t)b * NN + tj * 128) * NP;

    // global->smem: thread t -> row = t>>1, half = t&1 (4 chunks of 16B each)
    int grow = tid >> 1, ghalf = tid & 1;
    size_t goff = (size_t)grow * NP + ghalf * 32;
    uint32_t sw[4];
#pragma unroll
    for (int q = 0; q < 4; q++)
        sw[q] = (uint32_t)grow * 128 + (((ghalf * 4 + q) ^ (grow & 7)) << 4);

    float acc[4][4][4];
#pragma unroll
    for (int i = 0; i < 4; i++)
#pragma unroll
        for (int j = 0; j < 4; j++)
#pragma unroll
            for (int q = 0; q < 4; q++) acc[i][j][q] = 0.f;

    int arow = wm * 64 + (lane & 15);
    int acg  = lane >> 4;
    int brow = wn * 32 + (lane & 7);
    int bcg  = (lane >> 3) & 1;

    auto load_buf = [&](int buf, int kc) {
        uint32_t bb = sb + buf * 32768;
        const __nv_bfloat16* ga = srcA + goff + kc * 64;
        const __nv_bfloat16* gb = srcB + goff + kc * 64;
#pragma unroll
        for (int q = 0; q < 4; q++) {
            CP_ASYNC16(bb + sw[q], ga + q * 8);
            CP_ASYNC16(bb + 16384 + sw[q], gb + q * 8);
        }
    };

    load_buf(0, 0);
    CP_COMMIT();

    for (int kc = 0; kc < 16; kc++) {
        if (kc + 1 < 16) { load_buf((kc + 1) & 1, kc + 1); CP_COMMIT(); }
        if (kc + 1 < 16) { CP_WAIT(1); } else { CP_WAIT(0); }
        __syncthreads();

        uint32_t bb = sb + (kc & 1) * 32768;
#pragma unroll
        for (int ks = 0; ks < 4; ks++) {
            uint32_t aR[4][4], bR[4][2];
#pragma unroll
            for (int im = 0; im < 4; im++) {
                int r = arow + im * 16;
                uint32_t ad = bb + (uint32_t)r * 128 +
                              ((((ks * 2) + acg) ^ (r & 7)) << 4);
                ldsm_x4(aR[im][0], aR[im][1], aR[im][2], aR[im][3], ad);
            }
#pragma unroll
            for (int in = 0; in < 4; in++) {
                int r = brow + in * 8;
                uint32_t bd = bb + 16384 + (uint32_t)r * 128 +
                              ((((ks * 2) + bcg) ^ (r & 7)) << 4);
                ldsm_x2(bR[in][0], bR[in][1], bd);
            }
#pragma unroll
            for (int im = 0; im < 4; im++)
#pragma unroll
                for (int in = 0; in < 4; in++)
                    mma16816(acc[im][in], aR[im], bR[in]);
        }
        __syncthreads();
    }

    // ---- epilogue: store RAW + fused histogram (reuse smem) ----
    unsigned int* shist = (unsigned int*)smem;
    for (int x = tid; x < 4096; x += 256) shist[x] = 0;
    __syncthreads();

    float* Rb = g_RAW + (size_t)b * NN * NN;
    int r0 = ti * 128 + wm * 64 + (lane >> 2);
    int c0 = tj * 128 + wn * 32 + (lane & 3) * 2;
#pragma unroll
    for (int im = 0; im < 4; im++) {
#pragma unroll
        for (int in = 0; in < 4; in++) {
            int gi0 = r0 + im * 16;
            int gj  = c0 + in * 8;
            float* d0 = &Rb[(size_t)gi0 * NN + gj];
            float* d1 = &Rb[(size_t)(gi0 + 8) * NN + gj];
            d0[0] = acc[im][in][0]; d0[1] = acc[im][in][1];
            d1[0] = acc[im][in][2]; d1[1] = acc[im][in][3];
            if (gj     > gi0)     atomicAdd(&shist[mono_key(acc[im][in][0]) >> 20], 1u);
            if (gj + 1 > gi0)     atomicAdd(&shist[mono_key(acc[im][in][1]) >> 20], 1u);
            if (gj     > gi0 + 8) atomicAdd(&shist[mono_key(acc[im][in][2]) >> 20], 1u);
            if (gj + 1 > gi0 + 8) atomicAdd(&shist[mono_key(acc[im][in][3]) >> 20], 1u);
        }
    }
    __syncthreads();
    for (int x = tid; x < 4096; x += 256)
        if (shist[x]) atomicAdd(&g_hist[b][x], shist[x]);
}

// ---------------------------------------------------------------------------
// K4: pick bin containing rank-128, then step one margin bin down.
// one warp per batch, warp-scan from the top. <<<1, 256>>>
// ---------------------------------------------------------------------------
__global__ void k_select() {
    int b = threadIdx.x >> 5;
    int lane = threadIdx.x & 31;
    if (b >= NB) return;

    unsigned int cum = 0;
    int found = 0;
    for (int base = 4095; base >= 0; base -= 32) {
        int bin = base - lane;                      // lane 0 = highest bin
        unsigned int v = (bin >= 0) ? g_hist[b][bin] : 0u;
        unsigned int pre = v;
#pragma unroll
        for (int o = 1; o < 32; o <<= 1) {
            unsigned int t2 = __shfl_up_sync(0xFFFFFFFFu, pre, o);
            if (lane >= o) pre += t2;
        }
        unsigned int cl = cum + pre;
        unsigned int mask = __ballot_sync(0xFFFFFFFFu, cl >= NK);
        if (mask) { found = base - (__ffs(mask) - 1); break; }
        cum += __shfl_sync(0xFFFFFFFFu, pre, 31);
    }
    if (lane == 0) {
        int bin = found > 0 ? found - 1 : 0;        // margin bin for bf16 error
        g_thresh[b] = (unsigned int)bin << 20;
    }
}

// ---------------------------------------------------------------------------
// K5: collect candidates >= threshold (coalesced full-matrix float4 scan)
// ---------------------------------------------------------------------------
__global__ void k_collect() {
    int b = blockIdx.y;
    size_t x = ((size_t)blockIdx.x * 256 + threadIdx.x) * 4;
    unsigned int th = g_thresh[b];
    const float* Rb = g_RAW + (size_t)b * NN * NN;
    float4 v = *(const float4*)(Rb + x);
    int i = (int)(x >> 11);
    int j = (int)(x & 2047);
    float vv[4] = { v.x, v.y, v.z, v.w };
#pragma unroll
    for (int q = 0; q < 4; q++) {
        if (j + q > i && mono_key(vv[q]) >= th) {
            unsigned int pos = atomicAdd(&g_cnt[b], 1u);
            if (pos < CAND_CAP)
                g_cand[b][pos] =
                    (unsigned long long)(0xFFFFFFFFu - (unsigned)(x + q));
        }
    }
}

// ---------------------------------------------------------------------------
// K5b: exact rescore — one warp per candidate: fp32 dot S[i].O[j] (K=1024)
// ---------------------------------------------------------------------------
__global__ void k_rescore() {
    int b = blockIdx.y;
    unsigned int w = blockIdx.x * 8 + (threadIdx.x >> 5);
    int lane = threadIdx.x & 31;
    unsigned int cnt = g_cnt[b];
    if (cnt > CAND_CAP) cnt = CAND_CAP;
    if (w >= cnt) return;

    unsigned long long e = g_cand[b][w];
    unsigned int low = (unsigned int)e;
    unsigned int fl = (0xFFFFFFFFu - low) & 0x3FFFFFu;
    int i = fl >> 11, j = fl & 2047;

    const float* Si = g_S + ((size_t)b * NN + i) * NP;
    const float* Oj = g_O + ((size_t)b * NN + j) * NP;
    float acc = 0.f;
#pragma unroll
    for (int kk = 0; kk < 8; kk++) {
        float4 a = *(const float4*)&Si[kk * 128 + lane * 4];
        float4 c = *(const float4*)&Oj[kk * 128 + lane * 4];
        acc = fmaf(a.x, c.x, acc);
        acc = fmaf(a.y, c.y, acc);
        acc = fmaf(a.z, c.z, acc);
        acc = fmaf(a.w, c.w, acc);
    }
#pragma unroll
    for (int o = 16; o; o >>= 1) acc += __shfl_xor_sync(0xFFFFFFFFu, acc, o);

    if (lane == 0) {
        float sg = 1.0f / (1.0f + expf(-acc));
        unsigned int skey = __float_as_uint(sg) | 0x80000000u;
        g_cand[b][w] = ((unsigned long long)skey << 32) | low;
    }
}

// ---------------------------------------------------------------------------
// helper IoU
// ---------------------------------------------------------------------------
__device__ __forceinline__ float iou4(const float* A, const float* Bx) {
    float a1 = fmaxf(A[2] - A[0], 0.f) * fmaxf(A[3] - A[1], 0.f);
    float a2 = fmaxf(Bx[2] - Bx[0], 0.f) * fmaxf(Bx[3] - Bx[1], 0.f);
    float lx = fmaxf(A[0], Bx[0]), ly = fmaxf(A[1], Bx[1]);
    float rx = fminf(A[2], Bx[2]), ry = fminf(A[3], Bx[3]);
    float w = fmaxf(rx - lx, 0.f), h = fmaxf(ry - ly, 0.f);
    float inter = w * h;
    return inter / (a1 + a2 - inter + 1e-9f);
}

// ---------------------------------------------------------------------------
// K6: per-batch: bitonic sort candidates -> top-128 -> NMS -> gather
// ---------------------------------------------------------------------------
__global__ void k_final(const float* __restrict__ boxes,
                        const float* __restrict__ scores,
                        const float* __restrict__ features,
                        float* __restrict__ out) {
    extern __shared__ unsigned long long cand[];
    __shared__ float sbx[NK][4], obx[NK][4];
    __shared__ int   subj[NK], obj[NK], keep[NK], sel[NK];

    int b = blockIdx.x;
    int tid = threadIdx.x;
    unsigned int cnt = g_cnt[b];
    int n = (cnt < CAND_CAP) ? (int)cnt : CAND_CAP;
    int M = 128;
    while (M < n) M <<= 1;

    for (int i = tid; i < M; i += 256)
        cand[i] = (i < n) ? g_cand[b][i] : 0ULL;
    __syncthreads();

    for (int size = 2; size <= M; size <<= 1) {
        for (int stride = size >> 1; stride > 0; stride >>= 1) {
            for (int i = tid; i < M; i += 256) {
                int j = i ^ stride;
                if (j > i) {
                    unsigned long long a = cand[i], c2 = cand[j];
                    bool desc = ((i & size) == 0);
                    if (desc ? (a < c2) : (a > c2)) { cand[i] = c2; cand[j] = a; }
                }
            }
            __syncthreads();
        }
    }

    if (tid < NK) {
        unsigned int fl = (0xFFFFFFFFu - (unsigned)(cand[tid] & 0xFFFFFFFFu)) & 0x3FFFFFu;
        int si = fl >> 11;
        int oj = fl & 2047;
        subj[tid] = si; obj[tid] = oj;
        const float* bb = boxes + (size_t)b * NN * 4;
#pragma unroll
        for (int d = 0; d < 4; d++) {
            sbx[tid][d] = bb[si * 4 + d];
            obx[tid][d] = bb[oj * 4 + d];
        }
        keep[tid] = 1;
    }
    __syncthreads();

    for (int i = 0; i < NK; i++) {
        int ki = keep[i];
        if (tid < NK && tid > i && ki && keep[tid]) {
            float is = iou4(sbx[i], sbx[tid]);
            float io = iou4(obx[i], obx[tid]);
            if (is > IOU_THR && io > IOU_THR) keep[tid] = 0;
        }
        __syncthreads();
    }

    if (tid < NK) {
        float ps = sbx[tid][0] - sbx[tid][1]; ps *= ps;
        float po = obx[tid][0] - obx[tid][1]; po *= po;
        sel[tid] = (ps >= po) ? subj[tid] : obj[tid];
    }
    __syncthreads();

    const size_t OFF_F = (size_t)NB * NK * 8;
    const size_t OFF_S = OFF_F + (size_t)NB * NK * NP;

    for (int x = tid; x < NK * 8; x += 256) {
        int k = x >> 3, d = x & 7;
        float m = keep[k] ? 1.f : 0.f;
        float v = (d < 4) ? sbx[k][d] : obx[k][d - 4];
        out[((size_t)b * NK + k) * 8 + d] = v * m;
    }
    for (int x = tid; x < NK * NP; x += 256) {
        int k = x >> 10, p = x & 1023;
        float m = keep[k] ? 1.f : 0.f;
        out[OFF_F + ((size_t)b * NK + k) * NP + p] =
            features[((size_t)b * NN + sel[k]) * NP + p] * m;
    }
    for (int x = tid; x < NK * NC; x += 256) {
        int k = x / NC, c = x % NC;
        float m = keep[k] ? 1.f : 0.f;
        out[OFF_S + ((size_t)b * NK + k) * NC + c] =
            scores[((size_t)b * NN + sel[k]) * NC + c] * m;
    }
}

// ---------------------------------------------------------------------------
// launch
// ---------------------------------------------------------------------------
extern "C" void kernel_launch(void* const* d_in, const int* in_sizes, int n_in,
                              void* d_out, int out_size) {
    const float* boxes    = (const float*)d_in[0];
    const float* scores   = (const float*)d_in[1];
    const float* features = (const float*)d_in[2];
    const float* Ws       = (const float*)d_in[3];
    const float* bs       = (const float*)d_in[4];
    const float* Wo       = (const float*)d_in[5];
    const float* bo       = (const float*)d_in[6];
    float* out = (float*)d_out;
    (void)in_sizes; (void)n_in; (void)out_size;

    cudaFuncSetAttribute(k_gemm_mma, cudaFuncAttributeMaxDynamicSharedMemorySize,
                         SMEM_GEMM);
    cudaFuncSetAttribute(k_final, cudaFuncAttributeMaxDynamicSharedMemorySize,
                         CAND_CAP * 8);

    k_init<<<(NCM * NP + 255) / 256, 256>>>(Ws, Wo);
    k_gates<<<dim3(NP / 256, NN / 32, NB), 256>>>(scores, features, bs, bo);
    k_gemm_mma<<<dim3(136, NB), 256, SMEM_GEMM>>>();
    k_select<<<1, 256>>>();
    k_collect<<<dim3(NN * NN / 1024, NB), 256>>>();
    k_rescore<<<dim3(CAND_CAP / 8, NB), 256>>>();
    k_final<<<NB, 256, CAND_CAP * 8>>>(boxes, scores, features, out);
}

// round 8
// speedup vs baseline: 2.0287x; 1.0024x over previous
#include <cuda_runtime.h>
#include <cuda_bf16.h>
#include <cstdint>

// ---------------------------------------------------------------------------
// Problem constants
// ---------------------------------------------------------------------------
constexpr int NB  = 8;     // batches
constexpr int NN  = 2048;  // boxes per batch
constexpr int NC  = 91;    // classes
constexpr int NCM = 90;    // classes - 1
constexpr int NP  = 1024;  // feature dim
constexpr int NK  = 128;   // TOP_K
constexpr int CAND_CAP = 16384;
#define IOU_THR 0.7f

// ---------------------------------------------------------------------------
// Device scratch
// ---------------------------------------------------------------------------
__device__ float g_S  [(size_t)NB * NN * NP];   // fp32 for exact rescore
__device__ float g_O  [(size_t)NB * NN * NP];
__device__ __nv_bfloat16 g_Shi[(size_t)NB * NN * NP];
__device__ __nv_bfloat16 g_Ohi[(size_t)NB * NN * NP];
__device__ __nv_bfloat16 g_RAWh[(size_t)NB * NN * NN];  // approx raw (bf16)
__device__ float g_WtS[NCM * NP];
__device__ float g_WtO[NCM * NP];
__device__ unsigned int       g_hist[NB][4096];
__device__ unsigned int       g_thresh[NB];
__device__ unsigned int       g_cnt[NB];
__device__ unsigned long long g_cand[NB][CAND_CAP];

__device__ __forceinline__ unsigned int mono_key(float f) {
    unsigned int u = __float_as_uint(f);
    return (u & 0x80000000u) ? ~u : (u | 0x80000000u);
}

// ---------------------------------------------------------------------------
// PTX helpers (sm_80-era: mma.sync / ldmatrix / cp.async — valid on sm_100)
// ---------------------------------------------------------------------------
__device__ __forceinline__ uint32_t smem_u32(const void* p) {
    uint32_t a;
    asm("{ .reg .u64 t; cvta.to.shared.u64 t, %1; cvt.u32.u64 %0, t; }"
        : "=r"(a) : "l"(p));
    return a;
}
#define CP_ASYNC16(dst, src) \
    asm volatile("cp.async.ca.shared.global [%0], [%1], 16;" :: "r"(dst), "l"(src))
#define CP_COMMIT()  asm volatile("cp.async.commit_group;" ::: "memory")
#define CP_WAIT(n)   asm volatile("cp.async.wait_group %0;" :: "n"(n) : "memory")

__device__ __forceinline__ void ldsm_x4(uint32_t& r0, uint32_t& r1,
                                        uint32_t& r2, uint32_t& r3, uint32_t a) {
    asm volatile("ldmatrix.sync.aligned.m8n8.x4.shared.b16 {%0,%1,%2,%3}, [%4];"
                 : "=r"(r0), "=r"(r1), "=r"(r2), "=r"(r3) : "r"(a));
}
__device__ __forceinline__ void ldsm_x2(uint32_t& r0, uint32_t& r1, uint32_t a) {
    asm volatile("ldmatrix.sync.aligned.m8n8.x2.shared.b16 {%0,%1}, [%2];"
                 : "=r"(r0), "=r"(r1) : "r"(a));
}
__device__ __forceinline__ void mma16816(float* d, const uint32_t* a,
                                         const uint32_t* b) {
    asm volatile(
        "mma.sync.aligned.m16n8k16.row.col.f32.bf16.bf16.f32 "
        "{%0,%1,%2,%3}, {%4,%5,%6,%7}, {%8,%9}, {%0,%1,%2,%3};"
        : "+f"(d[0]), "+f"(d[1]), "+f"(d[2]), "+f"(d[3])
        : "r"(a[0]), "r"(a[1]), "r"(a[2]), "r"(a[3]), "r"(b[0]), "r"(b[1]));
}

// ---------------------------------------------------------------------------
// K0: transpose W matrices, zero histograms / counters
// ---------------------------------------------------------------------------
__global__ void k_init(const float* __restrict__ Ws, const float* __restrict__ Wo) {
    int idx = blockIdx.x * 256 + threadIdx.x;
    if (idx < NCM * NP) {
        int p = idx / NCM, c = idx % NCM;
        g_WtS[c * NP + p] = Ws[idx];
        g_WtO[c * NP + p] = Wo[idx];
    }
    if (idx < NB * 4096) ((unsigned int*)g_hist)[idx] = 0;
    if (idx < NB)        g_cnt[idx] = 0;
}

// ---------------------------------------------------------------------------
// K1: gates  s = (scores[:, :90] @ W_s^T + b_s) * f
// writes fp32 (exact rescore) + bf16 (HMMA approx)
// ---------------------------------------------------------------------------
__global__ void __launch_bounds__(256, 2)
k_gates(const float* __restrict__ scores, const float* __restrict__ features,
        const float* __restrict__ bsub,   const float* __restrict__ bobj) {
    __shared__ float sc[32 * NCM];
    int b  = blockIdx.z;
    int r0 = blockIdx.y * 32;
    int p0 = blockIdx.x * 256;
    int tid = threadIdx.x;

    for (int x = tid; x < 32 * NCM; x += 256) {
        int r = x / NCM, c = x % NCM;
        sc[x] = scores[((size_t)(b * NN + r0 + r)) * NC + c];
    }
    __syncthreads();

    int px = tid & 31;
    int ry = tid >> 5;
    int pb = p0 + px * 8;

    float aS[4][8], aO[4][8];
#pragma unroll
    for (int i = 0; i < 4; i++)
#pragma unroll
        for (int j = 0; j < 8; j++) { aS[i][j] = 0.f; aO[i][j] = 0.f; }

    for (int c = 0; c < NCM; c++) {
        float ws[8], wo[8];
        *(float4*)&ws[0] = *(const float4*)&g_WtS[c * NP + pb];
        *(float4*)&ws[4] = *(const float4*)&g_WtS[c * NP + pb + 4];
        *(float4*)&wo[0] = *(const float4*)&g_WtO[c * NP + pb];
        *(float4*)&wo[4] = *(const float4*)&g_WtO[c * NP + pb + 4];
#pragma unroll
        for (int rr = 0; rr < 4; rr++) {
            float v = sc[(ry * 4 + rr) * NCM + c];
#pragma unroll
            for (int j = 0; j < 8; j++) {
                aS[rr][j] = fmaf(v, ws[j], aS[rr][j]);
                aO[rr][j] = fmaf(v, wo[j], aO[rr][j]);
            }
        }
    }

    float bS[8], bO[8];
    *(float4*)&bS[0] = *(const float4*)&bsub[pb];
    *(float4*)&bS[4] = *(const float4*)&bsub[pb + 4];
    *(float4*)&bO[0] = *(const float4*)&bobj[pb];
    *(float4*)&bO[4] = *(const float4*)&bobj[pb + 4];

#pragma unroll
    for (int rr = 0; rr < 4; rr++) {
        int r = r0 + ry * 4 + rr;
        size_t base = ((size_t)b * NN + r) * NP + pb;
        float fv[8];
        *(float4*)&fv[0] = *(const float4*)&features[base];
        *(float4*)&fv[4] = *(const float4*)&features[base + 4];
        float so[8], oo[8];
        __nv_bfloat16 sh[8], oh[8];
#pragma unroll
        for (int j = 0; j < 8; j++) {
            so[j] = (aS[rr][j] + bS[j]) * fv[j];
            oo[j] = (aO[rr][j] + bO[j]) * fv[j];
            sh[j] = __float2bfloat16(so[j]);
            oh[j] = __float2bfloat16(oo[j]);
        }
        *(float4*)&g_S[base]     = *(float4*)&so[0];
        *(float4*)&g_S[base + 4] = *(float4*)&so[4];
        *(float4*)&g_O[base]     = *(float4*)&oo[0];
        *(float4*)&g_O[base + 4] = *(float4*)&oo[4];
        *(uint4*)&g_Shi[base] = *(uint4*)sh;
        *(uint4*)&g_Ohi[base] = *(uint4*)oh;
    }
}

// ---------------------------------------------------------------------------
// K2: HMMA GEMM  raw ~= S @ O^T (single-term bf16), upper-tri tiles only
// 128x128 tile, BK=64, 8 warps (2x4), cp.async double buffer
// epilogue: bf16 RAW store + WARP-AGGREGATED 12-bit histogram
// ---------------------------------------------------------------------------
constexpr int SMEM_GEMM = 2 * 2 * 128 * 128;   // 65536

__global__ void __launch_bounds__(256, 2) k_gemm_mma() {
    extern __shared__ char smem[];
    uint32_t sb = smem_u32(smem);

    int b = blockIdx.y;
    int t = blockIdx.x;
    int ti = 0;
    while (t >= 16 - ti) { t -= 16 - ti; ti++; }
    int tj = ti + t;

    int tid = threadIdx.x, wid = tid >> 5, lane = tid & 31;
    int wm = wid >> 2, wn = wid & 3;

    const __nv_bfloat16* srcA = g_Shi + ((size_t)b * NN + ti * 128) * NP;
    const __nv_bfloat16* srcB = g_Ohi + ((size_t)b * NN + tj * 128) * NP;

    int grow = tid >> 1, ghalf = tid & 1;
    size_t goff = (size_t)grow * NP + ghalf * 32;
    uint32_t sw[4];
#pragma unroll
    for (int q = 0; q < 4; q++)
        sw[q] = (uint32_t)grow * 128 + (((ghalf * 4 + q) ^ (grow & 7)) << 4);

    float acc[4][4][4];
#pragma unroll
    for (int i = 0; i < 4; i++)
#pragma unroll
        for (int j = 0; j < 4; j++)
#pragma unroll
            for (int q = 0; q < 4; q++) acc[i][j][q] = 0.f;

    int arow = wm * 64 + (lane & 15);
    int acg  = lane >> 4;
    int brow = wn * 32 + (lane & 7);
    int bcg  = (lane >> 3) & 1;

    auto load_buf = [&](int buf, int kc) {
        uint32_t bb = sb + buf * 32768;
        const __nv_bfloat16* ga = srcA + goff + kc * 64;
        const __nv_bfloat16* gb = srcB + goff + kc * 64;
#pragma unroll
        for (int q = 0; q < 4; q++) {
            CP_ASYNC16(bb + sw[q], ga + q * 8);
            CP_ASYNC16(bb + 16384 + sw[q], gb + q * 8);
        }
    };

    load_buf(0, 0);
    CP_COMMIT();

    for (int kc = 0; kc < 16; kc++) {
        if (kc + 1 < 16) { load_buf((kc + 1) & 1, kc + 1); CP_COMMIT(); }
        if (kc + 1 < 16) { CP_WAIT(1); } else { CP_WAIT(0); }
        __syncthreads();

        uint32_t bb = sb + (kc & 1) * 32768;
#pragma unroll
        for (int ks = 0; ks < 4; ks++) {
            uint32_t aR[4][4], bR[4][2];
#pragma unroll
            for (int im = 0; im < 4; im++) {
                int r = arow + im * 16;
                uint32_t ad = bb + (uint32_t)r * 128 +
                              ((((ks * 2) + acg) ^ (r & 7)) << 4);
                ldsm_x4(aR[im][0], aR[im][1], aR[im][2], aR[im][3], ad);
            }
#pragma unroll
            for (int in = 0; in < 4; in++) {
                int r = brow + in * 8;
                uint32_t bd = bb + 16384 + (uint32_t)r * 128 +
                              ((((ks * 2) + bcg) ^ (r & 7)) << 4);
                ldsm_x2(bR[in][0], bR[in][1], bd);
            }
#pragma unroll
            for (int im = 0; im < 4; im++)
#pragma unroll
                for (int in = 0; in < 4; in++)
                    mma16816(acc[im][in], aR[im], bR[in]);
        }
        __syncthreads();
    }

    // ---- epilogue: bf16 RAW store + warp-aggregated histogram ----
    unsigned int* shist = (unsigned int*)smem;
    for (int x = tid; x < 4096; x += 256) shist[x] = 0;
    __syncthreads();

    __nv_bfloat16* Rb = g_RAWh + (size_t)b * NN * NN;
    int r0 = ti * 128 + wm * 64 + (lane >> 2);
    int c0 = tj * 128 + wn * 32 + (lane & 3) * 2;
#pragma unroll
    for (int im = 0; im < 4; im++) {
#pragma unroll
        for (int in = 0; in < 4; in++) {
            int gi0 = r0 + im * 16;
            int gj  = c0 + in * 8;
            __nv_bfloat162 p0, p1;
            p0.x = __float2bfloat16(acc[im][in][0]);
            p0.y = __float2bfloat16(acc[im][in][1]);
            p1.x = __float2bfloat16(acc[im][in][2]);
            p1.y = __float2bfloat16(acc[im][in][3]);
            *(__nv_bfloat162*)&Rb[(size_t)gi0 * NN + gj]       = p0;
            *(__nv_bfloat162*)&Rb[(size_t)(gi0 + 8) * NN + gj] = p1;
#pragma unroll
            for (int q = 0; q < 4; q++) {
                int gi  = gi0 + ((q >= 2) ? 8 : 0);
                int gjj = gj + (q & 1);
                bool valid = gjj > gi;
                unsigned int bin = valid ? (mono_key(acc[im][in][q]) >> 20)
                                         : 0xFFFFFFFFu;
                unsigned int m = __match_any_sync(0xFFFFFFFFu, bin);
                int leader = __ffs(m) - 1;
                if (valid && lane == leader)
                    atomicAdd(&shist[bin], __popc(m));
            }
        }
    }
    __syncthreads();
    for (int x = tid; x < 4096; x += 256)
        if (shist[x]) atomicAdd(&g_hist[b][x], shist[x]);
}

// ---------------------------------------------------------------------------
// K4: pick bin containing rank-128, step one margin bin down.
// one block per batch, 256 threads, parallel loads + suffix scan
// ---------------------------------------------------------------------------
__global__ void k_select() {
    __shared__ unsigned int part[256];
    int b = blockIdx.x;
    int t = threadIdx.x;

    unsigned int v[16];
    unsigned int s = 0;
#pragma unroll
    for (int k = 0; k < 16; k++) { v[k] = g_hist[b][t * 16 + k]; s += v[k]; }
    part[t] = s;
    __syncthreads();

    // suffix sums: part[t] = sum of segments t..255
    for (int off = 1; off < 256; off <<= 1) {
        unsigned int add = (t + off < 256) ? part[t + off] : 0u;
        __syncthreads();
        part[t] += add;
        __syncthreads();
    }

    unsigned int above = (t < 255) ? part[t + 1] : 0u;
    if (above < NK && part[t] >= NK) {   // crossing segment (exactly one)
        unsigned int c = above;
        int bin = 0;
        for (int k = 15; k >= 0; k--) {
            c += v[k];
            if (c >= NK) { bin = t * 16 + k; break; }
        }
        if (bin > 0) bin -= 1;           // margin bin for bf16 error
        g_thresh[b] = (unsigned int)bin << 20;
    }
}

// ---------------------------------------------------------------------------
// K5: collect candidates >= threshold (bf16 scan, 8 values per thread)
// ---------------------------------------------------------------------------
__global__ void k_collect() {
    int b = blockIdx.y;
    size_t x = ((size_t)blockIdx.x * 256 + threadIdx.x) * 8;
    unsigned int th = g_thresh[b];
    const __nv_bfloat16* Rb = g_RAWh + (size_t)b * NN * NN;
    uint4 pk = *(const uint4*)(Rb + x);
    unsigned int w32[4] = { pk.x, pk.y, pk.z, pk.w };
    int i = (int)(x >> 11);
    int j = (int)(x & 2047);
#pragma unroll
    for (int q = 0; q < 8; q++) {
        unsigned short u = (unsigned short)(w32[q >> 1] >> ((q & 1) * 16));
        float f = __bfloat162float(__ushort_as_bfloat16(u));
        if (j + q > i && mono_key(f) >= th) {
            unsigned int pos = atomicAdd(&g_cnt[b], 1u);
            if (pos < CAND_CAP)
                g_cand[b][pos] =
                    (unsigned long long)(0xFFFFFFFFu - (unsigned)(x + q));
        }
    }
}

// ---------------------------------------------------------------------------
// K5b: exact rescore — one warp per candidate: fp32 dot S[i].O[j] (K=1024)
// ---------------------------------------------------------------------------
__global__ void k_rescore() {
    int b = blockIdx.y;
    unsigned int w = blockIdx.x * 8 + (threadIdx.x >> 5);
    int lane = threadIdx.x & 31;
    unsigned int cnt = g_cnt[b];
    if (cnt > CAND_CAP) cnt = CAND_CAP;
    if (w >= cnt) return;

    unsigned long long e = g_cand[b][w];
    unsigned int low = (unsigned int)e;
    unsigned int fl = (0xFFFFFFFFu - low) & 0x3FFFFFu;
    int i = fl >> 11, j = fl & 2047;

    const float* Si = g_S + ((size_t)b * NN + i) * NP;
    const float* Oj = g_O + ((size_t)b * NN + j) * NP;
    float acc = 0.f;
#pragma unroll
    for (int kk = 0; kk < 8; kk++) {
        float4 a = *(const float4*)&Si[kk * 128 + lane * 4];
        float4 c = *(const float4*)&Oj[kk * 128 + lane * 4];
        acc = fmaf(a.x, c.x, acc);
        acc = fmaf(a.y, c.y, acc);
        acc = fmaf(a.z, c.z, acc);
        acc = fmaf(a.w, c.w, acc);
    }
#pragma unroll
    for (int o = 16; o; o >>= 1) acc += __shfl_xor_sync(0xFFFFFFFFu, acc, o);

    if (lane == 0) {
        float sg = 1.0f / (1.0f + expf(-acc));
        unsigned int skey = __float_as_uint(sg) | 0x80000000u;
        g_cand[b][w] = ((unsigned long long)skey << 32) | low;
    }
}

// ---------------------------------------------------------------------------
// helper IoU
// ---------------------------------------------------------------------------
__device__ __forceinline__ float iou4(const float* A, const float* Bx) {
    float a1 = fmaxf(A[2] - A[0], 0.f) * fmaxf(A[3] - A[1], 0.f);
    float a2 = fmaxf(Bx[2] - Bx[0], 0.f) * fmaxf(Bx[3] - Bx[1], 0.f);
    float lx = fmaxf(A[0], Bx[0]), ly = fmaxf(A[1], Bx[1]);
    float rx = fminf(A[2], Bx[2]), ry = fminf(A[3], Bx[3]);
    float w = fmaxf(rx - lx, 0.f), h = fmaxf(ry - ly, 0.f);
    float inter = w * h;
    return inter / (a1 + a2 - inter + 1e-9f);
}

// ---------------------------------------------------------------------------
// K6: per-batch: bitonic sort candidates -> top-128 -> NMS -> gather
// ---------------------------------------------------------------------------
__global__ void k_final(const float* __restrict__ boxes,
                        const float* __restrict__ scores,
                        const float* __restrict__ features,
                        float* __restrict__ out) {
    extern __shared__ unsigned long long cand[];
    __shared__ float sbx[NK][4], obx[NK][4];
    __shared__ int   subj[NK], obj[NK], keep[NK], sel[NK];

    int b = blockIdx.x;
    int tid = threadIdx.x;
    unsigned int cnt = g_cnt[b];
    int n = (cnt < CAND_CAP) ? (int)cnt : CAND_CAP;
    int M = 128;
    while (M < n) M <<= 1;

    for (int i = tid; i < M; i += 256)
        cand[i] = (i < n) ? g_cand[b][i] : 0ULL;
    __syncthreads();

    for (int size = 2; size <= M; size <<= 1) {
        for (int stride = size >> 1; stride > 0; stride >>= 1) {
            for (int i = tid; i < M; i += 256) {
                int j = i ^ stride;
                if (j > i) {
                    unsigned long long a = cand[i], c2 = cand[j];
                    bool desc = ((i & size) == 0);
                    if (desc ? (a < c2) : (a > c2)) { cand[i] = c2; cand[j] = a; }
                }
            }
            __syncthreads();
        }
    }

    if (tid < NK) {
        unsigned int fl = (0xFFFFFFFFu - (unsigned)(cand[tid] & 0xFFFFFFFFu)) & 0x3FFFFFu;
        int si = fl >> 11;
        int oj = fl & 2047;
        subj[tid] = si; obj[tid] = oj;
        const float* bb = boxes + (size_t)b * NN * 4;
#pragma unroll
        for (int d = 0; d < 4; d++) {
            sbx[tid][d] = bb[si * 4 + d];
            obx[tid][d] = bb[oj * 4 + d];
        }
        keep[tid] = 1;
    }
    __syncthreads();

    for (int i = 0; i < NK; i++) {
        int ki = keep[i];
        if (tid < NK && tid > i && ki && keep[tid]) {
            float is = iou4(sbx[i], sbx[tid]);
            float io = iou4(obx[i], obx[tid]);
            if (is > IOU_THR && io > IOU_THR) keep[tid] = 0;
        }
        __syncthreads();
    }

    if (tid < NK) {
        float ps = sbx[tid][0] - sbx[tid][1]; ps *= ps;
        float po = obx[tid][0] - obx[tid][1]; po *= po;
        sel[tid] = (ps >= po) ? subj[tid] : obj[tid];
    }
    __syncthreads();

    const size_t OFF_F = (size_t)NB * NK * 8;
    const size_t OFF_S = OFF_F + (size_t)NB * NK * NP;

    for (int x = tid; x < NK * 8; x += 256) {
        int k = x >> 3, d = x & 7;
        float m = keep[k] ? 1.f : 0.f;
        float v = (d < 4) ? sbx[k][d] : obx[k][d - 4];
        out[((size_t)b * NK + k) * 8 + d] = v * m;
    }
    for (int x = tid; x < NK * NP; x += 256) {
        int k = x >> 10, p = x & 1023;
        float m = keep[k] ? 1.f : 0.f;
        out[OFF_F + ((size_t)b * NK + k) * NP + p] =
            features[((size_t)b * NN + sel[k]) * NP + p] * m;
    }
    for (int x = tid; x < NK * NC; x += 256) {
        int k = x / NC, c = x % NC;
        float m = keep[k] ? 1.f : 0.f;
        out[OFF_S + ((size_t)b * NK + k) * NC + c] =
            scores[((size_t)b * NN + sel[k]) * NC + c] * m;
    }
}

// ---------------------------------------------------------------------------
// launch
// ---------------------------------------------------------------------------
extern "C" void kernel_launch(void* const* d_in, const int* in_sizes, int n_in,
                              void* d_out, int out_size) {
    const float* boxes    = (const float*)d_in[0];
    const float* scores   = (const float*)d_in[1];
    const float* features = (const float*)d_in[2];
    const float* Ws       = (const float*)d_in[3];
    const float* bs       = (const float*)d_in[4];
    const float* Wo       = (const float*)d_in[5];
    const float* bo       = (const float*)d_in[6];
    float* out = (float*)d_out;
    (void)in_sizes; (void)n_in; (void)out_size;

    cudaFuncSetAttribute(k_gemm_mma, cudaFuncAttributeMaxDynamicSharedMemorySize,
                         SMEM_GEMM);
    cudaFuncSetAttribute(k_final, cudaFuncAttributeMaxDynamicSharedMemorySize,
                         CAND_CAP * 8);

    k_init<<<(NCM * NP + 255) / 256, 256>>>(Ws, Wo);
    k_gates<<<dim3(NP / 256, NN / 32, NB), 256>>>(scores, features, bs, bo);
    k_gemm_mma<<<dim3(136, NB), 256, SMEM_GEMM>>>();
    k_select<<<NB, 256>>>();
    k_collect<<<dim3(NN * NN / (256 * 8), NB), 256>>>();
    k_rescore<<<dim3(CAND_CAP / 8, NB), 256>>>();
    k_final<<<NB, 256, CAND_CAP * 8>>>(boxes, scores, features, out);
}